// round 1
// baseline (speedup 1.0000x reference)
#include <cuda_runtime.h>
#include <cuda_bf16.h>
#include <math.h>

// Problem constants
#define Bb_ 2
#define Ss_ 2048
#define Dd_ 2048
#define Hh_ 16
#define HKV_ 2
#define HD_ 128
#define MROWS (Bb_ * Ss_)          // 4096
#define NKV (HKV_ * HD_)           // 256

// Scratch (allocation-free: __device__ globals)
__device__ float g_Q[(size_t)MROWS * Dd_];
__device__ float g_K[(size_t)MROWS * NKV];
__device__ float g_V[(size_t)MROWS * NKV];
__device__ float g_O[(size_t)MROWS * Dd_];

// ---------------------------------------------------------------------------
// Generic fp32 SGEMM: C[M,N] = A[M,K] @ B[K,N], all row-major.
// 128x128 tile, BK=8, 256 threads, 8x8 microtile per thread.
// M,N multiples of 128; K multiple of 8 (true for all our shapes).
// ---------------------------------------------------------------------------
__global__ __launch_bounds__(256) void sgemm128(const float* __restrict__ A,
                                                const float* __restrict__ Bm,
                                                float* __restrict__ C,
                                                int M, int N, int K)
{
    __shared__ float As[8][128];   // transposed: As[k][m]
    __shared__ float Bs[8][128];   // Bs[k][n]

    const int t  = threadIdx.x;
    const int tx = t & 15;         // 0..15 -> n microtile
    const int ty = t >> 4;         // 0..15 -> m microtile
    const int bx = blockIdx.x;     // N tile
    const int by = blockIdx.y;     // M tile

    const float* Ab = A + (size_t)by * 128 * K;
    const float* Bb = Bm + (size_t)bx * 128;

    float acc[8][8];
#pragma unroll
    for (int i = 0; i < 8; ++i)
#pragma unroll
        for (int j = 0; j < 8; ++j) acc[i][j] = 0.0f;

    const int arow = t >> 1;           // 0..127
    const int acol = (t & 1) * 4;      // 0 or 4
    const int brow = t >> 5;           // 0..7
    const int bcol = (t & 31) * 4;     // 0..124

    for (int k0 = 0; k0 < K; k0 += 8) {
        float4 av = *(const float4*)(Ab + (size_t)arow * K + k0 + acol);
        float4 bv = *(const float4*)(Bb + (size_t)(k0 + brow) * N + bcol);
        __syncthreads();
        As[acol + 0][arow] = av.x;
        As[acol + 1][arow] = av.y;
        As[acol + 2][arow] = av.z;
        As[acol + 3][arow] = av.w;
        *(float4*)&Bs[brow][bcol] = bv;
        __syncthreads();
#pragma unroll
        for (int kk = 0; kk < 8; ++kk) {
            float a[8], b[8];
            *(float4*)(a)     = *(const float4*)&As[kk][ty * 8];
            *(float4*)(a + 4) = *(const float4*)&As[kk][ty * 8 + 4];
            *(float4*)(b)     = *(const float4*)&Bs[kk][tx * 8];
            *(float4*)(b + 4) = *(const float4*)&Bs[kk][tx * 8 + 4];
#pragma unroll
            for (int i = 0; i < 8; ++i)
#pragma unroll
                for (int j = 0; j < 8; ++j)
                    acc[i][j] = fmaf(a[i], b[j], acc[i][j]);
        }
    }

#pragma unroll
    for (int i = 0; i < 8; ++i) {
        const size_t r = (size_t)(by * 128 + ty * 8 + i) * N + bx * 128 + tx * 8;
        *(float4*)(C + r)     = make_float4(acc[i][0], acc[i][1], acc[i][2], acc[i][3]);
        *(float4*)(C + r + 4) = make_float4(acc[i][4], acc[i][5], acc[i][6], acc[i][7]);
    }
}

// ---------------------------------------------------------------------------
// RoPE (half-split / rotate_half convention, matching the reference):
//   out[i]    = x[i]*cos(p*f_i)    - x[i+64]*sin(p*f_i)
//   out[i+64] = x[i+64]*cos(p*f_i) + x[i]*sin(p*f_i)
// buf: [B*S, nh, 128] contiguous. One thread per (row, head, pair).
// ---------------------------------------------------------------------------
__global__ void rope_kernel(float* __restrict__ buf, int nh, int total)
{
    int idx = blockIdx.x * blockDim.x + threadIdx.x;
    if (idx >= total) return;
    int i    = idx & 63;               // pair index 0..63
    int hh   = (idx >> 6) % nh;
    int srow = idx / (64 * nh);        // 0..B*S-1
    int pos  = srow & (Ss_ - 1);       // position within sequence

    // inv_freq computed in double (accurate), angle in fp32 like the reference
    float inv = (float)exp(-(double)i * (log(10000.0) / 64.0));
    float ang = (float)pos * inv;
    float sn, cs;
    sincosf(ang, &sn, &cs);

    size_t base = (size_t)srow * (nh * HD_) + (size_t)hh * HD_ + i;
    float x1 = buf[base];
    float x2 = buf[base + 64];
    buf[base]      = x1 * cs - x2 * sn;
    buf[base + 64] = x2 * cs + x1 * sn;
}

// ---------------------------------------------------------------------------
// Causal flash attention, fp32.
// Grid: (S/64, H, B). 256 threads. BQ = BK = 64, HD = 128.
// SMEM: Qs[128][64] (d-major), Ks[128][64] (d-major), Vs[64][128], Ps[64][68].
// Thread (tx=t&15, ty=t>>4) owns q-rows 4*ty..4*ty+3.
//   S phase: 4x4 microtile (k-cols 4*tx..4*tx+3)
//   O phase: 4x8 microtile (d-cols 8*tx..8*tx+7)
// Row softmax state reduced across the 16 tx-lanes via shfl_xor (width 16).
// ---------------------------------------------------------------------------
#define FLASH_SMEM_FLOATS (128 * 64 + 128 * 64 + 64 * 128 + 64 * 68)
#define FLASH_SMEM_BYTES (FLASH_SMEM_FLOATS * 4)

__global__ __launch_bounds__(256) void flash_attn(const float* __restrict__ Q,
                                                  const float* __restrict__ Kg_,
                                                  const float* __restrict__ Vg_,
                                                  float* __restrict__ O)
{
    extern __shared__ float sm[];
    float* Qs = sm;                    // [128][64]  Qs[d*64 + q]
    float* Ks = Qs + 128 * 64;         // [128][64]  Ks[d*64 + k]
    float* Vs = Ks + 128 * 64;         // [64][128]  Vs[k*128 + d]
    float* Ps = Vs + 64 * 128;         // [64][68]   Ps[q*68 + k]

    const int qb = blockIdx.x;
    const int h  = blockIdx.y;
    const int b  = blockIdx.z;
    const int kvh = h % HKV_;

    const int t  = threadIdx.x;
    const int tx = t & 15;
    const int ty = t >> 4;

    const float scale = rsqrtf((float)HD_);

    // Load Q tile (64 rows x 128 dims), store d-major, pre-scaled.
    {
        const int row = t & 63;
        const int dg0 = t >> 6;        // 0..3
        const float* Qg = Q + ((size_t)(b * Ss_ + qb * 64)) * Dd_ + h * HD_;
#pragma unroll
        for (int it = 0; it < 8; ++it) {
            int dg = dg0 + 4 * it;     // 0..31 (float4 group)
            float4 v = *(const float4*)(Qg + (size_t)row * Dd_ + dg * 4);
            Qs[(4 * dg + 0) * 64 + row] = v.x * scale;
            Qs[(4 * dg + 1) * 64 + row] = v.y * scale;
            Qs[(4 * dg + 2) * 64 + row] = v.z * scale;
            Qs[(4 * dg + 3) * 64 + row] = v.w * scale;
        }
    }

    float m_[4], l_[4], o_[4][8];
#pragma unroll
    for (int j = 0; j < 4; ++j) {
        m_[j] = -INFINITY;
        l_[j] = 0.0f;
#pragma unroll
        for (int i = 0; i < 8; ++i) o_[j][i] = 0.0f;
    }

    for (int kb = 0; kb <= qb; ++kb) {
        __syncthreads();   // previous tile fully consumed; Q store visible (kb=0)

        // Load K tile (d-major) and V tile (row-major)
        {
            const int row = t & 63;
            const int dg0 = t >> 6;
            const float* Kp = Kg_ + ((size_t)(b * Ss_ + kb * 64)) * NKV + kvh * HD_;
#pragma unroll
            for (int it = 0; it < 8; ++it) {
                int dg = dg0 + 4 * it;
                float4 v = *(const float4*)(Kp + (size_t)row * NKV + dg * 4);
                Ks[(4 * dg + 0) * 64 + row] = v.x;
                Ks[(4 * dg + 1) * 64 + row] = v.y;
                Ks[(4 * dg + 2) * 64 + row] = v.z;
                Ks[(4 * dg + 3) * 64 + row] = v.w;
            }
            const float* Vp = Vg_ + ((size_t)(b * Ss_ + kb * 64)) * NKV + kvh * HD_;
#pragma unroll
            for (int it = 0; it < 8; ++it) {
                int idx = t + 256 * it;
                int vr  = idx >> 5;       // 0..63
                int f4  = idx & 31;       // 0..31
                *(float4*)&Vs[vr * 128 + f4 * 4] =
                    *(const float4*)(Vp + (size_t)vr * NKV + f4 * 4);
            }
        }
        __syncthreads();

        // S = (Q*scale) @ K^T  -> 4x4 per thread
        float s[4][4];
#pragma unroll
        for (int j = 0; j < 4; ++j)
#pragma unroll
            for (int i = 0; i < 4; ++i) s[j][i] = 0.0f;

#pragma unroll 8
        for (int d = 0; d < 128; ++d) {
            float4 q4 = *(const float4*)&Qs[d * 64 + 4 * ty];
            float4 k4 = *(const float4*)&Ks[d * 64 + 4 * tx];
            float qv[4] = {q4.x, q4.y, q4.z, q4.w};
            float kv[4] = {k4.x, k4.y, k4.z, k4.w};
#pragma unroll
            for (int j = 0; j < 4; ++j)
#pragma unroll
                for (int i = 0; i < 4; ++i)
                    s[j][i] = fmaf(qv[j], kv[i], s[j][i]);
        }

        // Causal mask on the diagonal block
        if (kb == qb) {
#pragma unroll
            for (int j = 0; j < 4; ++j)
#pragma unroll
                for (int i = 0; i < 4; ++i)
                    if (4 * tx + i > 4 * ty + j) s[j][i] = -INFINITY;
        }

        // Online softmax update per owned row j
#pragma unroll
        for (int j = 0; j < 4; ++j) {
            float mx = fmaxf(fmaxf(s[j][0], s[j][1]), fmaxf(s[j][2], s[j][3]));
#pragma unroll
            for (int off = 8; off > 0; off >>= 1)
                mx = fmaxf(mx, __shfl_xor_sync(0xffffffffu, mx, off, 16));
            float mn = fmaxf(m_[j], mx);
            float al = __expf(m_[j] - mn);
            m_[j] = mn;
            float rs = 0.0f;
#pragma unroll
            for (int i = 0; i < 4; ++i) {
                float p = __expf(s[j][i] - mn);
                s[j][i] = p;
                rs += p;
            }
#pragma unroll
            for (int off = 8; off > 0; off >>= 1)
                rs += __shfl_xor_sync(0xffffffffu, rs, off, 16);
            l_[j] = l_[j] * al + rs;
#pragma unroll
            for (int i = 0; i < 8; ++i) o_[j][i] *= al;
            // stage P: Ps[q][k]
            *(float4*)&Ps[(4 * ty + j) * 68 + 4 * tx] =
                make_float4(s[j][0], s[j][1], s[j][2], s[j][3]);
        }
        __syncthreads();

        // O += P @ V  -> 4 rows x 8 d-cols per thread
#pragma unroll 4
        for (int k = 0; k < 64; ++k) {
            float4 v0 = *(const float4*)&Vs[k * 128 + 8 * tx];
            float4 v1 = *(const float4*)&Vs[k * 128 + 8 * tx + 4];
            float vv[8] = {v0.x, v0.y, v0.z, v0.w, v1.x, v1.y, v1.z, v1.w};
#pragma unroll
            for (int j = 0; j < 4; ++j) {
                float p = Ps[(4 * ty + j) * 68 + k];
#pragma unroll
                for (int i = 0; i < 8; ++i)
                    o_[j][i] = fmaf(p, vv[i], o_[j][i]);
            }
        }
    }

    // Epilogue: normalize and write O[b, q, h*128 + d]
    float* Og = O + ((size_t)(b * Ss_ + qb * 64)) * Dd_ + h * HD_;
#pragma unroll
    for (int j = 0; j < 4; ++j) {
        float inv = 1.0f / l_[j];
        int row = 4 * ty + j;
        *(float4*)(Og + (size_t)row * Dd_ + 8 * tx) =
            make_float4(o_[j][0] * inv, o_[j][1] * inv, o_[j][2] * inv, o_[j][3] * inv);
        *(float4*)(Og + (size_t)row * Dd_ + 8 * tx + 4) =
            make_float4(o_[j][4] * inv, o_[j][5] * inv, o_[j][6] * inv, o_[j][7] * inv);
    }
}

// ---------------------------------------------------------------------------
// Launch: x@Wq/Wk/Wv -> RoPE(Q,K) -> flash attention -> @Wo
// Inputs (metadata order): x, mask(unused; deterministically causal), Wq, Wk, Wv, Wo
// ---------------------------------------------------------------------------
extern "C" void kernel_launch(void* const* d_in, const int* in_sizes, int n_in,
                              void* d_out, int out_size)
{
    const float* x  = (const float*)d_in[0];
    const float* Wq = (const float*)d_in[2];
    const float* Wk = (const float*)d_in[3];
    const float* Wv = (const float*)d_in[4];
    const float* Wo = (const float*)d_in[5];
    float* out = (float*)d_out;

    float *Qp, *Kp, *Vp, *Op;
    cudaGetSymbolAddress((void**)&Qp, g_Q);
    cudaGetSymbolAddress((void**)&Kp, g_K);
    cudaGetSymbolAddress((void**)&Vp, g_V);
    cudaGetSymbolAddress((void**)&Op, g_O);

    // QKV projections
    sgemm128<<<dim3(Dd_ / 128, MROWS / 128), 256>>>(x, Wq, Qp, MROWS, Dd_, Dd_);
    sgemm128<<<dim3(NKV / 128, MROWS / 128), 256>>>(x, Wk, Kp, MROWS, NKV, Dd_);
    sgemm128<<<dim3(NKV / 128, MROWS / 128), 256>>>(x, Wv, Vp, MROWS, NKV, Dd_);

    // RoPE
    {
        int totq = MROWS * Hh_ * 64;
        rope_kernel<<<(totq + 255) / 256, 256>>>(Qp, Hh_, totq);
        int totk = MROWS * HKV_ * 64;
        rope_kernel<<<(totk + 255) / 256, 256>>>(Kp, HKV_, totk);
    }

    // Flash attention
    cudaFuncSetAttribute(flash_attn, cudaFuncAttributeMaxDynamicSharedMemorySize,
                         FLASH_SMEM_BYTES);
    flash_attn<<<dim3(Ss_ / 64, Hh_, Bb_), 256, FLASH_SMEM_BYTES>>>(Qp, Kp, Vp, Op);

    // Output projection
    sgemm128<<<dim3(Dd_ / 128, MROWS / 128), 256>>>(Op, Wo, out, MROWS, Dd_, Dd_);
}

// round 2
// speedup vs baseline: 1.0034x; 1.0034x over previous
#include <cuda_runtime.h>
#include <cuda_bf16.h>
#include <math.h>

// Problem constants
#define Bb_ 2
#define Ss_ 2048
#define Dd_ 2048
#define Hh_ 16
#define HKV_ 2
#define HD_ 128
#define MROWS (Bb_ * Ss_)          // 4096
#define NKV (HKV_ * HD_)           // 256

// Scratch (allocation-free: __device__ globals)
__device__ float g_Q[(size_t)MROWS * Dd_];
__device__ float g_K[(size_t)MROWS * NKV];
__device__ float g_V[(size_t)MROWS * NKV];
__device__ float g_O[(size_t)MROWS * Dd_];

// ---------------------------------------------------------------------------
// Generic fp32 SGEMM: C[M,N] = A[M,K] @ B[K,N], all row-major.
// 128x128 tile, BK=8, 256 threads, 8x8 microtile per thread.
// M,N multiples of 128; K multiple of 8 (true for all our shapes).
// ---------------------------------------------------------------------------
__global__ __launch_bounds__(256) void sgemm128(const float* __restrict__ A,
                                                const float* __restrict__ Bm,
                                                float* __restrict__ C,
                                                int M, int N, int K)
{
    __shared__ float As[8][128];   // transposed: As[k][m]
    __shared__ float Bs[8][128];   // Bs[k][n]

    const int t  = threadIdx.x;
    const int tx = t & 15;         // 0..15 -> n microtile
    const int ty = t >> 4;         // 0..15 -> m microtile
    const int bx = blockIdx.x;     // N tile
    const int by = blockIdx.y;     // M tile

    const float* Ab = A + (size_t)by * 128 * K;
    const float* Bb = Bm + (size_t)bx * 128;

    float acc[8][8];
#pragma unroll
    for (int i = 0; i < 8; ++i)
#pragma unroll
        for (int j = 0; j < 8; ++j) acc[i][j] = 0.0f;

    const int arow = t >> 1;           // 0..127
    const int acol = (t & 1) * 4;      // 0 or 4
    const int brow = t >> 5;           // 0..7
    const int bcol = (t & 31) * 4;     // 0..124

    for (int k0 = 0; k0 < K; k0 += 8) {
        float4 av = *(const float4*)(Ab + (size_t)arow * K + k0 + acol);
        float4 bv = *(const float4*)(Bb + (size_t)(k0 + brow) * N + bcol);
        __syncthreads();
        As[acol + 0][arow] = av.x;
        As[acol + 1][arow] = av.y;
        As[acol + 2][arow] = av.z;
        As[acol + 3][arow] = av.w;
        *(float4*)&Bs[brow][bcol] = bv;
        __syncthreads();
#pragma unroll
        for (int kk = 0; kk < 8; ++kk) {
            float a[8], b[8];
            *(float4*)(a)     = *(const float4*)&As[kk][ty * 8];
            *(float4*)(a + 4) = *(const float4*)&As[kk][ty * 8 + 4];
            *(float4*)(b)     = *(const float4*)&Bs[kk][tx * 8];
            *(float4*)(b + 4) = *(const float4*)&Bs[kk][tx * 8 + 4];
#pragma unroll
            for (int i = 0; i < 8; ++i)
#pragma unroll
                for (int j = 0; j < 8; ++j)
                    acc[i][j] = fmaf(a[i], b[j], acc[i][j]);
        }
    }

#pragma unroll
    for (int i = 0; i < 8; ++i) {
        const size_t r = (size_t)(by * 128 + ty * 8 + i) * N + bx * 128 + tx * 8;
        *(float4*)(C + r)     = make_float4(acc[i][0], acc[i][1], acc[i][2], acc[i][3]);
        *(float4*)(C + r + 4) = make_float4(acc[i][4], acc[i][5], acc[i][6], acc[i][7]);
    }
}

// ---------------------------------------------------------------------------
// RoPE (half-split / rotate_half convention, matching the reference):
//   out[i]    = x[i]*cos(p*f_i)    - x[i+64]*sin(p*f_i)
//   out[i+64] = x[i+64]*cos(p*f_i) + x[i]*sin(p*f_i)
// buf: [B*S, nh, 128] contiguous. One thread per (row, head, pair).
// ---------------------------------------------------------------------------
__global__ void rope_kernel(float* __restrict__ buf, int nh, int total)
{
    int idx = blockIdx.x * blockDim.x + threadIdx.x;
    if (idx >= total) return;
    int i    = idx & 63;               // pair index 0..63
    int hh   = (idx >> 6) % nh;
    int srow = idx / (64 * nh);        // 0..B*S-1
    int pos  = srow & (Ss_ - 1);       // position within sequence

    // inv_freq computed in double (accurate), angle in fp32 like the reference
    float inv = (float)exp(-(double)i * (log(10000.0) / 64.0));
    float ang = (float)pos * inv;
    float sn, cs;
    sincosf(ang, &sn, &cs);

    size_t base = (size_t)srow * (nh * HD_) + (size_t)hh * HD_ + i;
    float x1 = buf[base];
    float x2 = buf[base + 64];
    buf[base]      = x1 * cs - x2 * sn;
    buf[base + 64] = x2 * cs + x1 * sn;
}

// ---------------------------------------------------------------------------
// Causal flash attention, fp32.
// Grid: (S/64, H, B). 256 threads. BQ = BK = 64, HD = 128.
// SMEM: Qs[128][64] (d-major), Ks[128][64] (d-major), Vs[64][128], Ps[64][68].
// Thread (tx=t&15, ty=t>>4) owns q-rows 4*ty..4*ty+3.
//   S phase: 4x4 microtile (k-cols 4*tx..4*tx+3)
//   O phase: 4x8 microtile (d-cols 8*tx..8*tx+7)
// Row softmax state reduced across the 16 tx-lanes via shfl_xor (width 16).
// ---------------------------------------------------------------------------
#define FLASH_SMEM_FLOATS (128 * 64 + 128 * 64 + 64 * 128 + 64 * 68)
#define FLASH_SMEM_BYTES (FLASH_SMEM_FLOATS * 4)

__global__ __launch_bounds__(256) void flash_attn(const float* __restrict__ Q,
                                                  const float* __restrict__ Kg_,
                                                  const float* __restrict__ Vg_,
                                                  float* __restrict__ O)
{
    extern __shared__ float sm[];
    float* Qs = sm;                    // [128][64]  Qs[d*64 + q]
    float* Ks = Qs + 128 * 64;         // [128][64]  Ks[d*64 + k]
    float* Vs = Ks + 128 * 64;         // [64][128]  Vs[k*128 + d]
    float* Ps = Vs + 64 * 128;         // [64][68]   Ps[q*68 + k]

    const int qb = blockIdx.x;
    const int h  = blockIdx.y;
    const int b  = blockIdx.z;
    const int kvh = h % HKV_;

    const int t  = threadIdx.x;
    const int tx = t & 15;
    const int ty = t >> 4;

    const float scale = rsqrtf((float)HD_);

    // Load Q tile (64 rows x 128 dims), store d-major, pre-scaled.
    {
        const int row = t & 63;
        const int dg0 = t >> 6;        // 0..3
        const float* Qg = Q + ((size_t)(b * Ss_ + qb * 64)) * Dd_ + h * HD_;
#pragma unroll
        for (int it = 0; it < 8; ++it) {
            int dg = dg0 + 4 * it;     // 0..31 (float4 group)
            float4 v = *(const float4*)(Qg + (size_t)row * Dd_ + dg * 4);
            Qs[(4 * dg + 0) * 64 + row] = v.x * scale;
            Qs[(4 * dg + 1) * 64 + row] = v.y * scale;
            Qs[(4 * dg + 2) * 64 + row] = v.z * scale;
            Qs[(4 * dg + 3) * 64 + row] = v.w * scale;
        }
    }

    float m_[4], l_[4], o_[4][8];
#pragma unroll
    for (int j = 0; j < 4; ++j) {
        m_[j] = -INFINITY;
        l_[j] = 0.0f;
#pragma unroll
        for (int i = 0; i < 8; ++i) o_[j][i] = 0.0f;
    }

    for (int kb = 0; kb <= qb; ++kb) {
        __syncthreads();   // previous tile fully consumed; Q store visible (kb=0)

        // Load K tile (d-major) and V tile (row-major)
        {
            const int row = t & 63;
            const int dg0 = t >> 6;
            const float* Kp = Kg_ + ((size_t)(b * Ss_ + kb * 64)) * NKV + kvh * HD_;
#pragma unroll
            for (int it = 0; it < 8; ++it) {
                int dg = dg0 + 4 * it;
                float4 v = *(const float4*)(Kp + (size_t)row * NKV + dg * 4);
                Ks[(4 * dg + 0) * 64 + row] = v.x;
                Ks[(4 * dg + 1) * 64 + row] = v.y;
                Ks[(4 * dg + 2) * 64 + row] = v.z;
                Ks[(4 * dg + 3) * 64 + row] = v.w;
            }
            const float* Vp = Vg_ + ((size_t)(b * Ss_ + kb * 64)) * NKV + kvh * HD_;
#pragma unroll
            for (int it = 0; it < 8; ++it) {
                int idx = t + 256 * it;
                int vr  = idx >> 5;       // 0..63
                int f4  = idx & 31;       // 0..31
                *(float4*)&Vs[vr * 128 + f4 * 4] =
                    *(const float4*)(Vp + (size_t)vr * NKV + f4 * 4);
            }
        }
        __syncthreads();

        // S = (Q*scale) @ K^T  -> 4x4 per thread
        float s[4][4];
#pragma unroll
        for (int j = 0; j < 4; ++j)
#pragma unroll
            for (int i = 0; i < 4; ++i) s[j][i] = 0.0f;

#pragma unroll 8
        for (int d = 0; d < 128; ++d) {
            float4 q4 = *(const float4*)&Qs[d * 64 + 4 * ty];
            float4 k4 = *(const float4*)&Ks[d * 64 + 4 * tx];
            float qv[4] = {q4.x, q4.y, q4.z, q4.w};
            float kv[4] = {k4.x, k4.y, k4.z, k4.w};
#pragma unroll
            for (int j = 0; j < 4; ++j)
#pragma unroll
                for (int i = 0; i < 4; ++i)
                    s[j][i] = fmaf(qv[j], kv[i], s[j][i]);
        }

        // Causal mask on the diagonal block
        if (kb == qb) {
#pragma unroll
            for (int j = 0; j < 4; ++j)
#pragma unroll
                for (int i = 0; i < 4; ++i)
                    if (4 * tx + i > 4 * ty + j) s[j][i] = -INFINITY;
        }

        // Online softmax update per owned row j
#pragma unroll
        for (int j = 0; j < 4; ++j) {
            float mx = fmaxf(fmaxf(s[j][0], s[j][1]), fmaxf(s[j][2], s[j][3]));
#pragma unroll
            for (int off = 8; off > 0; off >>= 1)
                mx = fmaxf(mx, __shfl_xor_sync(0xffffffffu, mx, off, 16));
            float mn = fmaxf(m_[j], mx);
            float al = __expf(m_[j] - mn);
            m_[j] = mn;
            float rs = 0.0f;
#pragma unroll
            for (int i = 0; i < 4; ++i) {
                float p = __expf(s[j][i] - mn);
                s[j][i] = p;
                rs += p;
            }
#pragma unroll
            for (int off = 8; off > 0; off >>= 1)
                rs += __shfl_xor_sync(0xffffffffu, rs, off, 16);
            l_[j] = l_[j] * al + rs;
#pragma unroll
            for (int i = 0; i < 8; ++i) o_[j][i] *= al;
            // stage P: Ps[q][k]
            *(float4*)&Ps[(4 * ty + j) * 68 + 4 * tx] =
                make_float4(s[j][0], s[j][1], s[j][2], s[j][3]);
        }
        __syncthreads();

        // O += P @ V  -> 4 rows x 8 d-cols per thread
#pragma unroll 4
        for (int k = 0; k < 64; ++k) {
            float4 v0 = *(const float4*)&Vs[k * 128 + 8 * tx];
            float4 v1 = *(const float4*)&Vs[k * 128 + 8 * tx + 4];
            float vv[8] = {v0.x, v0.y, v0.z, v0.w, v1.x, v1.y, v1.z, v1.w};
#pragma unroll
            for (int j = 0; j < 4; ++j) {
                float p = Ps[(4 * ty + j) * 68 + k];
#pragma unroll
                for (int i = 0; i < 8; ++i)
                    o_[j][i] = fmaf(p, vv[i], o_[j][i]);
            }
        }
    }

    // Epilogue: normalize and write O[b, q, h*128 + d]
    float* Og = O + ((size_t)(b * Ss_ + qb * 64)) * Dd_ + h * HD_;
#pragma unroll
    for (int j = 0; j < 4; ++j) {
        float inv = 1.0f / l_[j];
        int row = 4 * ty + j;
        *(float4*)(Og + (size_t)row * Dd_ + 8 * tx) =
            make_float4(o_[j][0] * inv, o_[j][1] * inv, o_[j][2] * inv, o_[j][3] * inv);
        *(float4*)(Og + (size_t)row * Dd_ + 8 * tx + 4) =
            make_float4(o_[j][4] * inv, o_[j][5] * inv, o_[j][6] * inv, o_[j][7] * inv);
    }
}

// ---------------------------------------------------------------------------
// Launch: x@Wq/Wk/Wv -> RoPE(Q,K) -> flash attention -> @Wo
// Inputs (metadata order): x, mask(unused; deterministically causal), Wq, Wk, Wv, Wo
// ---------------------------------------------------------------------------
extern "C" void kernel_launch(void* const* d_in, const int* in_sizes, int n_in,
                              void* d_out, int out_size)
{
    const float* x  = (const float*)d_in[0];
    const float* Wq = (const float*)d_in[2];
    const float* Wk = (const float*)d_in[3];
    const float* Wv = (const float*)d_in[4];
    const float* Wo = (const float*)d_in[5];
    float* out = (float*)d_out;

    float *Qp, *Kp, *Vp, *Op;
    cudaGetSymbolAddress((void**)&Qp, g_Q);
    cudaGetSymbolAddress((void**)&Kp, g_K);
    cudaGetSymbolAddress((void**)&Vp, g_V);
    cudaGetSymbolAddress((void**)&Op, g_O);

    // QKV projections
    sgemm128<<<dim3(Dd_ / 128, MROWS / 128), 256>>>(x, Wq, Qp, MROWS, Dd_, Dd_);
    sgemm128<<<dim3(NKV / 128, MROWS / 128), 256>>>(x, Wk, Kp, MROWS, NKV, Dd_);
    sgemm128<<<dim3(NKV / 128, MROWS / 128), 256>>>(x, Wv, Vp, MROWS, NKV, Dd_);

    // RoPE
    {
        int totq = MROWS * Hh_ * 64;
        rope_kernel<<<(totq + 255) / 256, 256>>>(Qp, Hh_, totq);
        int totk = MROWS * HKV_ * 64;
        rope_kernel<<<(totk + 255) / 256, 256>>>(Kp, HKV_, totk);
    }

    // Flash attention
    cudaFuncSetAttribute(flash_attn, cudaFuncAttributeMaxDynamicSharedMemorySize,
                         FLASH_SMEM_BYTES);
    flash_attn<<<dim3(Ss_ / 64, Hh_, Bb_), 256, FLASH_SMEM_BYTES>>>(Qp, Kp, Vp, Op);

    // Output projection
    sgemm128<<<dim3(Dd_ / 128, MROWS / 128), 256>>>(Op, Wo, out, MROWS, Dd_, Dd_);
}

// round 4
// speedup vs baseline: 1.6851x; 1.6794x over previous
#include <cuda_runtime.h>
#include <cuda_bf16.h>
#include <math.h>
#include <stdint.h>

// Problem constants
#define Bb_ 2
#define Ss_ 2048
#define Dd_ 2048
#define Hh_ 16
#define HKV_ 2
#define HD_ 128
#define MROWS (Bb_ * Ss_)          // 4096
#define NKV (HKV_ * HD_)           // 256

// Scratch (allocation-free: __device__ globals)
__device__ float g_Q[(size_t)MROWS * Dd_];
__device__ float g_K[(size_t)MROWS * NKV];
__device__ float g_V[(size_t)MROWS * NKV];
__device__ float g_O[(size_t)MROWS * Dd_];
// bf16 split buffers (A side: x or O; B side: current weight)
__device__ __nv_bfloat16 g_Ah[(size_t)MROWS * Dd_];
__device__ __nv_bfloat16 g_Al[(size_t)MROWS * Dd_];
__device__ __nv_bfloat16 g_Bh[(size_t)Dd_ * Dd_];
__device__ __nv_bfloat16 g_Bl[(size_t)Dd_ * Dd_];

// ---------------------------------------------------------------------------
// Helpers
// ---------------------------------------------------------------------------
static __device__ __forceinline__ uint32_t smem_u32(const void* p) {
    uint32_t r;
    asm("{ .reg .u64 t; cvta.to.shared.u64 t, %1; cvt.u32.u64 %0, t; }"
        : "=r"(r) : "l"(p));
    return r;
}

static __device__ __forceinline__ void mma16816(float* c, const uint32_t* a,
                                                const uint32_t* b) {
    asm volatile(
        "mma.sync.aligned.m16n8k16.row.col.f32.bf16.bf16.f32 "
        "{%0,%1,%2,%3}, {%4,%5,%6,%7}, {%8,%9}, {%0,%1,%2,%3};"
        : "+f"(c[0]), "+f"(c[1]), "+f"(c[2]), "+f"(c[3])
        : "r"(a[0]), "r"(a[1]), "r"(a[2]), "r"(a[3]), "r"(b[0]), "r"(b[1]));
}

static __device__ __forceinline__ void ldsm_x4(uint32_t* r, uint32_t addr) {
    asm volatile("ldmatrix.sync.aligned.m8n8.x4.shared.b16 {%0,%1,%2,%3}, [%4];"
                 : "=r"(r[0]), "=r"(r[1]), "=r"(r[2]), "=r"(r[3]) : "r"(addr));
}

static __device__ __forceinline__ void ldsm_x2_t(uint32_t* r, uint32_t addr) {
    asm volatile("ldmatrix.sync.aligned.m8n8.x2.trans.shared.b16 {%0,%1}, [%2];"
                 : "=r"(r[0]), "=r"(r[1]) : "r"(addr));
}

// Split a pair of floats into packed bf16x2 hi + lo residual
static __device__ __forceinline__ void split2(float a, float b,
                                              uint32_t& hi, uint32_t& lo) {
    __nv_bfloat162 h = __floats2bfloat162_rn(a, b);
    float ra = a - __bfloat162float(h.x);
    float rb = b - __bfloat162float(h.y);
    __nv_bfloat162 l = __floats2bfloat162_rn(ra, rb);
    hi = *reinterpret_cast<uint32_t*>(&h);
    lo = *reinterpret_cast<uint32_t*>(&l);
}

// fp32 -> bf16 hi/lo split (one pass over unique data)
__global__ void convert_split_k(const float* __restrict__ in,
                                __nv_bfloat16* __restrict__ hi,
                                __nv_bfloat16* __restrict__ lo, int n)
{
    int i = (blockIdx.x * blockDim.x + threadIdx.x) * 4;
    if (i >= n) return;
    float4 v = *(const float4*)(in + i);
    uint32_t h0, l0, h1, l1;
    split2(v.x, v.y, h0, l0);
    split2(v.z, v.w, h1, l1);
    *(uint2*)(hi + i) = make_uint2(h0, h1);
    *(uint2*)(lo + i) = make_uint2(l0, l1);
}

// ---------------------------------------------------------------------------
// bf16x3 tensor-core GEMM via mma.sync (sm_80+ path; works on plain sm_100):
//   C[M,N] = A[M,K] @ B[K,N], A/B given as bf16 hi/lo pairs, fp32 accumulate.
// CTA tile 128x128, BK=64, 8 warps each 64x32 (warp grid 2m x 4n).
// SMEM: A [m][k] stride 72 halves (144B: ldmatrix conflict-free),
//       B [k][n] stride 136 halves (272B: conflict-free, coalesced stores).
// 3 precision passes: Ahi*Bhi + Ahi*Blo + Alo*Bhi.
// ---------------------------------------------------------------------------
#define SA_STRIDE 72
#define SB_STRIDE 136
#define SA_SZ (128 * SA_STRIDE)     // halves
#define SB_SZ (64 * SB_STRIDE)
#define GEMM_SMEM_BYTES ((2 * SA_SZ + 2 * SB_SZ) * 2)

__global__ __launch_bounds__(256, 2) void gemm_tc(const __nv_bfloat16* __restrict__ Ah,
                                                  const __nv_bfloat16* __restrict__ Al,
                                                  const __nv_bfloat16* __restrict__ Bh,
                                                  const __nv_bfloat16* __restrict__ Bl,
                                                  float* __restrict__ C,
                                                  int M, int N, int K)
{
    extern __shared__ __nv_bfloat16 sm[];
    __nv_bfloat16* sAh = sm;
    __nv_bfloat16* sAl = sAh + SA_SZ;
    __nv_bfloat16* sBh = sAl + SA_SZ;
    __nv_bfloat16* sBl = sBh + SB_SZ;

    const int t    = threadIdx.x;
    const int lane = t & 31;
    const int wid  = t >> 5;
    const int wm   = wid & 1;         // 0..1 -> 64-row half
    const int wn   = wid >> 1;        // 0..3 -> 32-col quarter
    const int n0   = blockIdx.x * 128;
    const int m0   = blockIdx.y * 128;

    float acc[4][4][4];
#pragma unroll
    for (int i = 0; i < 4; ++i)
#pragma unroll
        for (int j = 0; j < 4; ++j)
#pragma unroll
            for (int k = 0; k < 4; ++k) acc[i][j][k] = 0.0f;

    // Per-lane ldmatrix base addresses (bytes)
    const uint32_t A_LO = SA_SZ * 2;
    const uint32_t B_LO = SB_SZ * 2;
    const uint32_t a_addr = smem_u32(sAh) +
        (uint32_t)(((lane & 7) + ((lane >> 3) & 1) * 8 + wm * 64) * (SA_STRIDE * 2)) +
        (uint32_t)(((lane >> 4) & 1) * 16);
    const uint32_t b_addr = smem_u32(sBh) +
        (uint32_t)(((lane & 7) + ((lane >> 3) & 1) * 8) * (SB_STRIDE * 2)) +
        (uint32_t)(wn * 64);

    const int nch = K >> 6;
    for (int c = 0; c < nch; ++c) {
        const int k0 = c << 6;
        __syncthreads();

        // ---- A tiles (hi+lo): 128 rows x 64 halves, uint2 per thread x8 ----
        {
            const int r  = t >> 4;
            const int c4 = (t & 15) * 4;
            const size_t gA = (size_t)(m0 + r) * K + k0 + c4;
#pragma unroll
            for (int p = 0; p < 8; ++p) {
                const size_t g = gA + (size_t)(16 * p) * K;
                const int s = (r + 16 * p) * SA_STRIDE + c4;
                *(uint2*)&sAh[s] = *(const uint2*)(Ah + g);
                *(uint2*)&sAl[s] = *(const uint2*)(Al + g);
            }
        }
        // ---- B tiles (hi+lo): 64 rows x 128 halves, uint4 per thread x4 ----
        {
            const int kr = t >> 4;
            const int c8 = (t & 15) * 8;
#pragma unroll
            for (int i = 0; i < 4; ++i) {
                const size_t g = (size_t)(k0 + kr + 16 * i) * N + n0 + c8;
                const int s = (kr + 16 * i) * SB_STRIDE + c8;
                *(uint4*)&sBh[s] = *(const uint4*)(Bh + g);
                *(uint4*)&sBl[s] = *(const uint4*)(Bl + g);
            }
        }
        __syncthreads();

        // ---- 4 k16 steps x 3 precision passes ----
#pragma unroll
        for (int k16 = 0; k16 < 4; ++k16) {
            uint32_t bh[4][2], bl[4][2], af[4][4];
            const uint32_t bko = (uint32_t)(k16 * 16 * SB_STRIDE * 2);
#pragma unroll
            for (int nt = 0; nt < 4; ++nt) {
                ldsm_x2_t(bh[nt], b_addr + nt * 16 + bko);
                ldsm_x2_t(bl[nt], b_addr + B_LO + nt * 16 + bko);
            }
            const uint32_t ako = (uint32_t)(k16 * 32);
#pragma unroll
            for (int mt = 0; mt < 4; ++mt)
                ldsm_x4(af[mt], a_addr + mt * (16 * SA_STRIDE * 2) + ako);
#pragma unroll
            for (int mt = 0; mt < 4; ++mt)
#pragma unroll
                for (int nt = 0; nt < 4; ++nt) {
                    mma16816(acc[mt][nt], af[mt], bh[nt]);
                    mma16816(acc[mt][nt], af[mt], bl[nt]);
                }
#pragma unroll
            for (int mt = 0; mt < 4; ++mt)
                ldsm_x4(af[mt], a_addr + A_LO + mt * (16 * SA_STRIDE * 2) + ako);
#pragma unroll
            for (int mt = 0; mt < 4; ++mt)
#pragma unroll
                for (int nt = 0; nt < 4; ++nt)
                    mma16816(acc[mt][nt], af[mt], bh[nt]);
        }
    }

    // Epilogue: fragment layout -> gmem
    const int g  = lane >> 2;
    const int tid = lane & 3;
#pragma unroll
    for (int mt = 0; mt < 4; ++mt) {
        const int row = m0 + wm * 64 + mt * 16 + g;
#pragma unroll
        for (int nt = 0; nt < 4; ++nt) {
            const int col = n0 + wn * 32 + nt * 8 + tid * 2;
            *(float2*)(C + (size_t)row * N + col) =
                make_float2(acc[mt][nt][0], acc[mt][nt][1]);
            *(float2*)(C + (size_t)(row + 8) * N + col) =
                make_float2(acc[mt][nt][2], acc[mt][nt][3]);
        }
    }
}

// ---------------------------------------------------------------------------
// RoPE (unchanged, validated)
// ---------------------------------------------------------------------------
__global__ void rope_kernel(float* __restrict__ buf, int nh, int total)
{
    int idx = blockIdx.x * blockDim.x + threadIdx.x;
    if (idx >= total) return;
    int i    = idx & 63;
    int hh   = (idx >> 6) % nh;
    int srow = idx / (64 * nh);
    int pos  = srow & (Ss_ - 1);

    float inv = (float)exp(-(double)i * (log(10000.0) / 64.0));
    float ang = (float)pos * inv;
    float sn, cs;
    sincosf(ang, &sn, &cs);

    size_t base = (size_t)srow * (nh * HD_) + (size_t)hh * HD_ + i;
    float x1 = buf[base];
    float x2 = buf[base + 64];
    buf[base]      = x1 * cs - x2 * sn;
    buf[base + 64] = x2 * cs + x1 * sn;
}

// ---------------------------------------------------------------------------
// Causal flash attention, fp32 (unchanged, validated)
// ---------------------------------------------------------------------------
#define FLASH_SMEM_FLOATS (128 * 64 + 128 * 64 + 64 * 128 + 64 * 68)
#define FLASH_SMEM_BYTES (FLASH_SMEM_FLOATS * 4)

__global__ __launch_bounds__(256) void flash_attn(const float* __restrict__ Q,
                                                  const float* __restrict__ Kg_,
                                                  const float* __restrict__ Vg_,
                                                  float* __restrict__ O)
{
    extern __shared__ float smf[];
    float* Qs = smf;
    float* Ks = Qs + 128 * 64;
    float* Vs = Ks + 128 * 64;
    float* Ps = Vs + 64 * 128;

    const int qb = blockIdx.x;
    const int h  = blockIdx.y;
    const int b  = blockIdx.z;
    const int kvh = h % HKV_;

    const int t  = threadIdx.x;
    const int tx = t & 15;
    const int ty = t >> 4;

    const float scale = rsqrtf((float)HD_);

    {
        const int row = t & 63;
        const int dg0 = t >> 6;
        const float* Qg = Q + ((size_t)(b * Ss_ + qb * 64)) * Dd_ + h * HD_;
#pragma unroll
        for (int it = 0; it < 8; ++it) {
            int dg = dg0 + 4 * it;
            float4 v = *(const float4*)(Qg + (size_t)row * Dd_ + dg * 4);
            Qs[(4 * dg + 0) * 64 + row] = v.x * scale;
            Qs[(4 * dg + 1) * 64 + row] = v.y * scale;
            Qs[(4 * dg + 2) * 64 + row] = v.z * scale;
            Qs[(4 * dg + 3) * 64 + row] = v.w * scale;
        }
    }

    float m_[4], l_[4], o_[4][8];
#pragma unroll
    for (int j = 0; j < 4; ++j) {
        m_[j] = -INFINITY;
        l_[j] = 0.0f;
#pragma unroll
        for (int i = 0; i < 8; ++i) o_[j][i] = 0.0f;
    }

    for (int kb = 0; kb <= qb; ++kb) {
        __syncthreads();

        {
            const int row = t & 63;
            const int dg0 = t >> 6;
            const float* Kp = Kg_ + ((size_t)(b * Ss_ + kb * 64)) * NKV + kvh * HD_;
#pragma unroll
            for (int it = 0; it < 8; ++it) {
                int dg = dg0 + 4 * it;
                float4 v = *(const float4*)(Kp + (size_t)row * NKV + dg * 4);
                Ks[(4 * dg + 0) * 64 + row] = v.x;
                Ks[(4 * dg + 1) * 64 + row] = v.y;
                Ks[(4 * dg + 2) * 64 + row] = v.z;
                Ks[(4 * dg + 3) * 64 + row] = v.w;
            }
            const float* Vp = Vg_ + ((size_t)(b * Ss_ + kb * 64)) * NKV + kvh * HD_;
#pragma unroll
            for (int it = 0; it < 8; ++it) {
                int idx = t + 256 * it;
                int vr  = idx >> 5;
                int f4  = idx & 31;
                *(float4*)&Vs[vr * 128 + f4 * 4] =
                    *(const float4*)(Vp + (size_t)vr * NKV + f4 * 4);
            }
        }
        __syncthreads();

        float s[4][4];
#pragma unroll
        for (int j = 0; j < 4; ++j)
#pragma unroll
            for (int i = 0; i < 4; ++i) s[j][i] = 0.0f;

#pragma unroll 8
        for (int d = 0; d < 128; ++d) {
            float4 q4 = *(const float4*)&Qs[d * 64 + 4 * ty];
            float4 k4 = *(const float4*)&Ks[d * 64 + 4 * tx];
            float qv[4] = {q4.x, q4.y, q4.z, q4.w};
            float kv[4] = {k4.x, k4.y, k4.z, k4.w};
#pragma unroll
            for (int j = 0; j < 4; ++j)
#pragma unroll
                for (int i = 0; i < 4; ++i)
                    s[j][i] = fmaf(qv[j], kv[i], s[j][i]);
        }

        if (kb == qb) {
#pragma unroll
            for (int j = 0; j < 4; ++j)
#pragma unroll
                for (int i = 0; i < 4; ++i)
                    if (4 * tx + i > 4 * ty + j) s[j][i] = -INFINITY;
        }

#pragma unroll
        for (int j = 0; j < 4; ++j) {
            float mx = fmaxf(fmaxf(s[j][0], s[j][1]), fmaxf(s[j][2], s[j][3]));
#pragma unroll
            for (int off = 8; off > 0; off >>= 1)
                mx = fmaxf(mx, __shfl_xor_sync(0xffffffffu, mx, off, 16));
            float mn = fmaxf(m_[j], mx);
            float al = __expf(m_[j] - mn);
            m_[j] = mn;
            float rs = 0.0f;
#pragma unroll
            for (int i = 0; i < 4; ++i) {
                float p = __expf(s[j][i] - mn);
                s[j][i] = p;
                rs += p;
            }
#pragma unroll
            for (int off = 8; off > 0; off >>= 1)
                rs += __shfl_xor_sync(0xffffffffu, rs, off, 16);
            l_[j] = l_[j] * al + rs;
#pragma unroll
            for (int i = 0; i < 8; ++i) o_[j][i] *= al;
            *(float4*)&Ps[(4 * ty + j) * 68 + 4 * tx] =
                make_float4(s[j][0], s[j][1], s[j][2], s[j][3]);
        }
        __syncthreads();

#pragma unroll 4
        for (int k = 0; k < 64; ++k) {
            float4 v0 = *(const float4*)&Vs[k * 128 + 8 * tx];
            float4 v1 = *(const float4*)&Vs[k * 128 + 8 * tx + 4];
            float vv[8] = {v0.x, v0.y, v0.z, v0.w, v1.x, v1.y, v1.z, v1.w};
#pragma unroll
            for (int j = 0; j < 4; ++j) {
                float p = Ps[(4 * ty + j) * 68 + k];
#pragma unroll
                for (int i = 0; i < 8; ++i)
                    o_[j][i] = fmaf(p, vv[i], o_[j][i]);
            }
        }
    }

    float* Og = O + ((size_t)(b * Ss_ + qb * 64)) * Dd_ + h * HD_;
#pragma unroll
    for (int j = 0; j < 4; ++j) {
        float inv = 1.0f / l_[j];
        int row = 4 * ty + j;
        *(float4*)(Og + (size_t)row * Dd_ + 8 * tx) =
            make_float4(o_[j][0] * inv, o_[j][1] * inv, o_[j][2] * inv, o_[j][3] * inv);
        *(float4*)(Og + (size_t)row * Dd_ + 8 * tx + 4) =
            make_float4(o_[j][4] * inv, o_[j][5] * inv, o_[j][6] * inv, o_[j][7] * inv);
    }
}

// ---------------------------------------------------------------------------
// Launch
// ---------------------------------------------------------------------------
extern "C" void kernel_launch(void* const* d_in, const int* in_sizes, int n_in,
                              void* d_out, int out_size)
{
    const float* x  = (const float*)d_in[0];
    const float* Wq = (const float*)d_in[2];
    const float* Wk = (const float*)d_in[3];
    const float* Wv = (const float*)d_in[4];
    const float* Wo = (const float*)d_in[5];
    float* out = (float*)d_out;

    float *Qp, *Kp, *Vp, *Op;
    __nv_bfloat16 *Ahp, *Alp, *Bhp, *Blp;
    cudaGetSymbolAddress((void**)&Qp, g_Q);
    cudaGetSymbolAddress((void**)&Kp, g_K);
    cudaGetSymbolAddress((void**)&Vp, g_V);
    cudaGetSymbolAddress((void**)&Op, g_O);
    cudaGetSymbolAddress((void**)&Ahp, g_Ah);
    cudaGetSymbolAddress((void**)&Alp, g_Al);
    cudaGetSymbolAddress((void**)&Bhp, g_Bh);
    cudaGetSymbolAddress((void**)&Blp, g_Bl);

    cudaFuncSetAttribute(gemm_tc, cudaFuncAttributeMaxDynamicSharedMemorySize,
                         GEMM_SMEM_BYTES);

    const int nX  = MROWS * Dd_;        // 8.4M
    const int nWq = Dd_ * Dd_;          // 4.2M
    const int nWk = Dd_ * NKV;          // 0.5M

    // x -> bf16 hi/lo (A side)
    convert_split_k<<<nX / 1024, 256>>>(x, Ahp, Alp, nX);

    // Q = x @ Wq
    convert_split_k<<<nWq / 1024, 256>>>(Wq, Bhp, Blp, nWq);
    gemm_tc<<<dim3(Dd_ / 128, MROWS / 128), 256, GEMM_SMEM_BYTES>>>(
        Ahp, Alp, Bhp, Blp, Qp, MROWS, Dd_, Dd_);

    // K = x @ Wk
    convert_split_k<<<nWk / 1024, 256>>>(Wk, Bhp, Blp, nWk);
    gemm_tc<<<dim3(NKV / 128, MROWS / 128), 256, GEMM_SMEM_BYTES>>>(
        Ahp, Alp, Bhp, Blp, Kp, MROWS, NKV, Dd_);

    // V = x @ Wv
    convert_split_k<<<nWk / 1024, 256>>>(Wv, Bhp, Blp, nWk);
    gemm_tc<<<dim3(NKV / 128, MROWS / 128), 256, GEMM_SMEM_BYTES>>>(
        Ahp, Alp, Bhp, Blp, Vp, MROWS, NKV, Dd_);

    // RoPE
    {
        int totq = MROWS * Hh_ * 64;
        rope_kernel<<<(totq + 255) / 256, 256>>>(Qp, Hh_, totq);
        int totk = MROWS * HKV_ * 64;
        rope_kernel<<<(totk + 255) / 256, 256>>>(Kp, HKV_, totk);
    }

    // Flash attention
    cudaFuncSetAttribute(flash_attn, cudaFuncAttributeMaxDynamicSharedMemorySize,
                         FLASH_SMEM_BYTES);
    flash_attn<<<dim3(Ss_ / 64, Hh_, Bb_), 256, FLASH_SMEM_BYTES>>>(Qp, Kp, Vp, Op);

    // out = O @ Wo
    convert_split_k<<<nX / 1024, 256>>>(Op, Ahp, Alp, nX);
    convert_split_k<<<nWq / 1024, 256>>>(Wo, Bhp, Blp, nWq);
    gemm_tc<<<dim3(Dd_ / 128, MROWS / 128), 256, GEMM_SMEM_BYTES>>>(
        Ahp, Alp, Bhp, Blp, out, MROWS, Dd_, Dd_);
}

// round 5
// speedup vs baseline: 3.6901x; 2.1899x over previous
#include <cuda_runtime.h>
#include <cuda_bf16.h>
#include <cuda_fp16.h>
#include <math.h>
#include <stdint.h>

// Problem constants
#define Bb_ 2
#define Ss_ 2048
#define Dd_ 2048
#define Hh_ 16
#define HKV_ 2
#define HD_ 128
#define MROWS (Bb_ * Ss_)          // 4096
#define NKV (HKV_ * HD_)           // 256

// Scratch (allocation-free: __device__ globals)
__device__ float g_Q[(size_t)MROWS * Dd_];
__device__ float g_K[(size_t)MROWS * NKV];
__device__ float g_V[(size_t)MROWS * NKV];
__device__ float g_O[(size_t)MROWS * Dd_];
// bf16 split buffers for GEMM
__device__ __nv_bfloat16 g_Ah[(size_t)MROWS * Dd_];
__device__ __nv_bfloat16 g_Al[(size_t)MROWS * Dd_];
__device__ __nv_bfloat16 g_Bh[(size_t)Dd_ * Dd_];
__device__ __nv_bfloat16 g_Bl[(size_t)Dd_ * Dd_];
// fp16 buffers for attention
__device__ __half g_Qh[(size_t)MROWS * Dd_];
__device__ __half g_Kh[(size_t)MROWS * NKV];
__device__ __half g_Vh[(size_t)MROWS * NKV];

// ---------------------------------------------------------------------------
// Helpers
// ---------------------------------------------------------------------------
static __device__ __forceinline__ uint32_t smem_u32(const void* p) {
    uint32_t r;
    asm("{ .reg .u64 t; cvta.to.shared.u64 t, %1; cvt.u32.u64 %0, t; }"
        : "=r"(r) : "l"(p));
    return r;
}

static __device__ __forceinline__ void mma16816(float* c, const uint32_t* a,
                                                const uint32_t* b) {
    asm volatile(
        "mma.sync.aligned.m16n8k16.row.col.f32.bf16.bf16.f32 "
        "{%0,%1,%2,%3}, {%4,%5,%6,%7}, {%8,%9}, {%0,%1,%2,%3};"
        : "+f"(c[0]), "+f"(c[1]), "+f"(c[2]), "+f"(c[3])
        : "r"(a[0]), "r"(a[1]), "r"(a[2]), "r"(a[3]), "r"(b[0]), "r"(b[1]));
}

static __device__ __forceinline__ void mma16816h(float* c, const uint32_t* a,
                                                 const uint32_t* b) {
    asm volatile(
        "mma.sync.aligned.m16n8k16.row.col.f32.f16.f16.f32 "
        "{%0,%1,%2,%3}, {%4,%5,%6,%7}, {%8,%9}, {%0,%1,%2,%3};"
        : "+f"(c[0]), "+f"(c[1]), "+f"(c[2]), "+f"(c[3])
        : "r"(a[0]), "r"(a[1]), "r"(a[2]), "r"(a[3]), "r"(b[0]), "r"(b[1]));
}

static __device__ __forceinline__ void ldsm_x4(uint32_t* r, uint32_t addr) {
    asm volatile("ldmatrix.sync.aligned.m8n8.x4.shared.b16 {%0,%1,%2,%3}, [%4];"
                 : "=r"(r[0]), "=r"(r[1]), "=r"(r[2]), "=r"(r[3]) : "r"(addr));
}

static __device__ __forceinline__ void ldsm_x4_t(uint32_t* r, uint32_t addr) {
    asm volatile("ldmatrix.sync.aligned.m8n8.x4.trans.shared.b16 {%0,%1,%2,%3}, [%4];"
                 : "=r"(r[0]), "=r"(r[1]), "=r"(r[2]), "=r"(r[3]) : "r"(addr));
}

static __device__ __forceinline__ void ldsm_x2_t(uint32_t* r, uint32_t addr) {
    asm volatile("ldmatrix.sync.aligned.m8n8.x2.trans.shared.b16 {%0,%1}, [%2];"
                 : "=r"(r[0]), "=r"(r[1]) : "r"(addr));
}

static __device__ __forceinline__ float ex2f(float x) {
    float y;
    asm("ex2.approx.f32 %0, %1;" : "=f"(y) : "f"(x));
    return y;
}

static __device__ __forceinline__ uint32_t packh2(float a, float b) {
    __half2 h = __floats2half2_rn(a, b);
    return *reinterpret_cast<uint32_t*>(&h);
}

// Split a pair of floats into packed bf16x2 hi + lo residual
static __device__ __forceinline__ void split2(float a, float b,
                                              uint32_t& hi, uint32_t& lo) {
    __nv_bfloat162 h = __floats2bfloat162_rn(a, b);
    float ra = a - __bfloat162float(h.x);
    float rb = b - __bfloat162float(h.y);
    __nv_bfloat162 l = __floats2bfloat162_rn(ra, rb);
    hi = *reinterpret_cast<uint32_t*>(&h);
    lo = *reinterpret_cast<uint32_t*>(&l);
}

// fp32 -> bf16 hi/lo split
__global__ void convert_split_k(const float* __restrict__ in,
                                __nv_bfloat16* __restrict__ hi,
                                __nv_bfloat16* __restrict__ lo, int n)
{
    int i = (blockIdx.x * blockDim.x + threadIdx.x) * 4;
    if (i >= n) return;
    float4 v = *(const float4*)(in + i);
    uint32_t h0, l0, h1, l1;
    split2(v.x, v.y, h0, l0);
    split2(v.z, v.w, h1, l1);
    *(uint2*)(hi + i) = make_uint2(h0, h1);
    *(uint2*)(lo + i) = make_uint2(l0, l1);
}

// fp32 -> fp16 with multiplier
__global__ void convert_half_k(const float* __restrict__ in,
                               __half* __restrict__ out, int n, float mult)
{
    int i = (blockIdx.x * blockDim.x + threadIdx.x) * 8;
    if (i >= n) return;
    float4 a = *(const float4*)(in + i);
    float4 b = *(const float4*)(in + i + 4);
    uint4 o;
    o.x = packh2(a.x * mult, a.y * mult);
    o.y = packh2(a.z * mult, a.w * mult);
    o.z = packh2(b.x * mult, b.y * mult);
    o.w = packh2(b.z * mult, b.w * mult);
    *(uint4*)(out + i) = o;
}

// ---------------------------------------------------------------------------
// bf16x3 tensor-core GEMM (validated R4)
// ---------------------------------------------------------------------------
#define SA_STRIDE 72
#define SB_STRIDE 136
#define SA_SZ (128 * SA_STRIDE)
#define SB_SZ (64 * SB_STRIDE)
#define GEMM_SMEM_BYTES ((2 * SA_SZ + 2 * SB_SZ) * 2)

__global__ __launch_bounds__(256, 2) void gemm_tc(const __nv_bfloat16* __restrict__ Ah,
                                                  const __nv_bfloat16* __restrict__ Al,
                                                  const __nv_bfloat16* __restrict__ Bh,
                                                  const __nv_bfloat16* __restrict__ Bl,
                                                  float* __restrict__ C,
                                                  int M, int N, int K)
{
    extern __shared__ __nv_bfloat16 smb[];
    __nv_bfloat16* sAh = smb;
    __nv_bfloat16* sAl = sAh + SA_SZ;
    __nv_bfloat16* sBh = sAl + SA_SZ;
    __nv_bfloat16* sBl = sBh + SB_SZ;

    const int t    = threadIdx.x;
    const int lane = t & 31;
    const int wid  = t >> 5;
    const int wm   = wid & 1;
    const int wn   = wid >> 1;
    const int n0   = blockIdx.x * 128;
    const int m0   = blockIdx.y * 128;

    float acc[4][4][4];
#pragma unroll
    for (int i = 0; i < 4; ++i)
#pragma unroll
        for (int j = 0; j < 4; ++j)
#pragma unroll
            for (int k = 0; k < 4; ++k) acc[i][j][k] = 0.0f;

    const uint32_t A_LO = SA_SZ * 2;
    const uint32_t B_LO = SB_SZ * 2;
    const uint32_t a_addr = smem_u32(sAh) +
        (uint32_t)(((lane & 7) + ((lane >> 3) & 1) * 8 + wm * 64) * (SA_STRIDE * 2)) +
        (uint32_t)(((lane >> 4) & 1) * 16);
    const uint32_t b_addr = smem_u32(sBh) +
        (uint32_t)(((lane & 7) + ((lane >> 3) & 1) * 8) * (SB_STRIDE * 2)) +
        (uint32_t)(wn * 64);

    const int nch = K >> 6;
    for (int c = 0; c < nch; ++c) {
        const int k0 = c << 6;
        __syncthreads();
        {
            const int r  = t >> 4;
            const int c4 = (t & 15) * 4;
            const size_t gA = (size_t)(m0 + r) * K + k0 + c4;
#pragma unroll
            for (int p = 0; p < 8; ++p) {
                const size_t g = gA + (size_t)(16 * p) * K;
                const int s = (r + 16 * p) * SA_STRIDE + c4;
                *(uint2*)&sAh[s] = *(const uint2*)(Ah + g);
                *(uint2*)&sAl[s] = *(const uint2*)(Al + g);
            }
        }
        {
            const int kr = t >> 4;
            const int c8 = (t & 15) * 8;
#pragma unroll
            for (int i = 0; i < 4; ++i) {
                const size_t g = (size_t)(k0 + kr + 16 * i) * N + n0 + c8;
                const int s = (kr + 16 * i) * SB_STRIDE + c8;
                *(uint4*)&sBh[s] = *(const uint4*)(Bh + g);
                *(uint4*)&sBl[s] = *(const uint4*)(Bl + g);
            }
        }
        __syncthreads();

#pragma unroll
        for (int k16 = 0; k16 < 4; ++k16) {
            uint32_t bh[4][2], bl[4][2], af[4][4];
            const uint32_t bko = (uint32_t)(k16 * 16 * SB_STRIDE * 2);
#pragma unroll
            for (int nt = 0; nt < 4; ++nt) {
                ldsm_x2_t(bh[nt], b_addr + nt * 16 + bko);
                ldsm_x2_t(bl[nt], b_addr + B_LO + nt * 16 + bko);
            }
            const uint32_t ako = (uint32_t)(k16 * 32);
#pragma unroll
            for (int mt = 0; mt < 4; ++mt)
                ldsm_x4(af[mt], a_addr + mt * (16 * SA_STRIDE * 2) + ako);
#pragma unroll
            for (int mt = 0; mt < 4; ++mt)
#pragma unroll
                for (int nt = 0; nt < 4; ++nt) {
                    mma16816(acc[mt][nt], af[mt], bh[nt]);
                    mma16816(acc[mt][nt], af[mt], bl[nt]);
                }
#pragma unroll
            for (int mt = 0; mt < 4; ++mt)
                ldsm_x4(af[mt], a_addr + A_LO + mt * (16 * SA_STRIDE * 2) + ako);
#pragma unroll
            for (int mt = 0; mt < 4; ++mt)
#pragma unroll
                for (int nt = 0; nt < 4; ++nt)
                    mma16816(acc[mt][nt], af[mt], bh[nt]);
        }
    }

    const int g   = lane >> 2;
    const int tid = lane & 3;
#pragma unroll
    for (int mt = 0; mt < 4; ++mt) {
        const int row = m0 + wm * 64 + mt * 16 + g;
#pragma unroll
        for (int nt = 0; nt < 4; ++nt) {
            const int col = n0 + wn * 32 + nt * 8 + tid * 2;
            *(float2*)(C + (size_t)row * N + col) =
                make_float2(acc[mt][nt][0], acc[mt][nt][1]);
            *(float2*)(C + (size_t)(row + 8) * N + col) =
                make_float2(acc[mt][nt][2], acc[mt][nt][3]);
        }
    }
}

// ---------------------------------------------------------------------------
// RoPE (unchanged, validated)
// ---------------------------------------------------------------------------
__global__ void rope_kernel(float* __restrict__ buf, int nh, int total)
{
    int idx = blockIdx.x * blockDim.x + threadIdx.x;
    if (idx >= total) return;
    int i    = idx & 63;
    int hh   = (idx >> 6) % nh;
    int srow = idx / (64 * nh);
    int pos  = srow & (Ss_ - 1);

    float inv = (float)exp(-(double)i * (log(10000.0) / 64.0));
    float ang = (float)pos * inv;
    float sn, cs;
    sincosf(ang, &sn, &cs);

    size_t base = (size_t)srow * (nh * HD_) + (size_t)hh * HD_ + i;
    float x1 = buf[base];
    float x2 = buf[base + 64];
    buf[base]      = x1 * cs - x2 * sn;
    buf[base + 64] = x2 * cs + x1 * sn;
}

// ---------------------------------------------------------------------------
// Tensor-core causal flash attention (fp16 mma, fp32 accum, exp2 softmax).
// Grid (S/128, H, B), 256 threads = 8 warps x 16 q-rows. BK=64.
// SMEM (half, stride 136): Qs[128], Ks[64], Vs[64]  -> conflict-free ldmatrix.
// Q is pre-scaled by (1/sqrt(128))*log2(e); softmax in base-2 domain.
// ---------------------------------------------------------------------------
#define FA_BQ 128
#define FA_BK 64
#define FA_STR 136
#define FA_SMEM ((FA_BQ + 2 * FA_BK) * FA_STR * 2)

__global__ __launch_bounds__(256) void flash_tc(const __half* __restrict__ Qh,
                                                const __half* __restrict__ Kh,
                                                const __half* __restrict__ Vh,
                                                float* __restrict__ O)
{
    extern __shared__ __half sh[];
    __half* Qs = sh;                         // [128][136]
    __half* Ks = Qs + FA_BQ * FA_STR;        // [64][136]
    __half* Vs = Ks + FA_BK * FA_STR;        // [64][136]

    const int qb = blockIdx.x, h = blockIdx.y, b = blockIdx.z;
    const int kvh = h % HKV_;
    const int t = threadIdx.x, lane = t & 31, w = t >> 5;
    const int q0 = qb * FA_BQ;
    const int wq0 = w * 16;

    // Load Q tile once
    {
#pragma unroll
        for (int i = 0; i < 8; ++i) {
            int linear = t + 256 * i;
            int row = linear >> 4;
            int c8 = (linear & 15) * 8;
            *(uint4*)&Qs[row * FA_STR + c8] =
                *(const uint4*)(Qh + (size_t)(b * Ss_ + q0 + row) * Dd_ + h * HD_ + c8);
        }
    }

    float oacc[16][4];
#pragma unroll
    for (int i = 0; i < 16; ++i)
#pragma unroll
        for (int j = 0; j < 4; ++j) oacc[i][j] = 0.0f;
    float mrow[2] = {-INFINITY, -INFINITY};
    float lrow[2] = {0.0f, 0.0f};

    const uint32_t qa = smem_u32(Qs) +
        (uint32_t)((wq0 + (lane & 15)) * (FA_STR * 2)) +
        (uint32_t)(((lane >> 4) & 1) * 16);
    // K (B operand, col-major natural): rows = kv pos, non-trans
    const uint32_t ka = smem_u32(Ks) +
        (uint32_t)(((lane & 7) + ((lane >> 4) & 1) * 8) * (FA_STR * 2)) +
        (uint32_t)(((lane >> 3) & 1) * 16);
    // V (B operand, row-major [kv][d]): trans
    const uint32_t va = smem_u32(Vs) +
        (uint32_t)(((lane & 7) + ((lane >> 3) & 1) * 8) * (FA_STR * 2)) +
        (uint32_t)(((lane >> 4) & 1) * 16);

    const int nkb = (q0 + FA_BQ) / FA_BK;
    for (int kb = 0; kb < nkb; ++kb) {
        const int k0 = kb * FA_BK;
        __syncthreads();
        // Load K and V tiles
        {
#pragma unroll
            for (int i = 0; i < 4; ++i) {
                int linear = t + 256 * i;
                int row = linear >> 4;
                int c8 = (linear & 15) * 8;
                size_t g = (size_t)(b * Ss_ + k0 + row) * NKV + kvh * HD_ + c8;
                *(uint4*)&Ks[row * FA_STR + c8] = *(const uint4*)(Kh + g);
                *(uint4*)&Vs[row * FA_STR + c8] = *(const uint4*)(Vh + g);
            }
        }
        __syncthreads();

        if (k0 <= q0 + wq0 + 15) {   // warp-uniform: skip fully-masked blocks
            float sacc[8][4];
#pragma unroll
            for (int i = 0; i < 8; ++i)
#pragma unroll
                for (int j = 0; j < 4; ++j) sacc[i][j] = 0.0f;

            // S = Q @ K^T over d=128 (8 k16 steps)
#pragma unroll
            for (int kk = 0; kk < 8; ++kk) {
                uint32_t af[4];
                ldsm_x4(af, qa + kk * 32);
#pragma unroll
                for (int np = 0; np < 4; ++np) {
                    uint32_t bf[4];
                    ldsm_x4(bf, ka + np * 16 * (FA_STR * 2) + kk * 32);
                    mma16816h(sacc[np * 2],     af, bf);
                    mma16816h(sacc[np * 2 + 1], af, bf + 2);
                }
            }

            // Causal mask (only near-diagonal blocks)
            if (k0 + FA_BK - 1 > q0 + wq0) {
                const int rbase = q0 + wq0 + (lane >> 2);
                const int cbase = k0 + (lane & 3) * 2;
#pragma unroll
                for (int nt = 0; nt < 8; ++nt)
#pragma unroll
                    for (int e = 0; e < 4; ++e) {
                        int col = cbase + nt * 8 + (e & 1);
                        int row = rbase + (e >> 1) * 8;
                        if (col > row) sacc[nt][e] = -INFINITY;
                    }
            }

            // Online softmax (base-2 domain)
#pragma unroll
            for (int r = 0; r < 2; ++r) {
                float mx = -INFINITY;
#pragma unroll
                for (int nt = 0; nt < 8; ++nt)
                    mx = fmaxf(mx, fmaxf(sacc[nt][2 * r], sacc[nt][2 * r + 1]));
                mx = fmaxf(mx, __shfl_xor_sync(0xffffffffu, mx, 1));
                mx = fmaxf(mx, __shfl_xor_sync(0xffffffffu, mx, 2));
                float mn = fmaxf(mrow[r], mx);
                float al = ex2f(mrow[r] - mn);
                mrow[r] = mn;
                float rs = 0.0f;
#pragma unroll
                for (int nt = 0; nt < 8; ++nt) {
                    float p0 = ex2f(sacc[nt][2 * r] - mn);
                    float p1 = ex2f(sacc[nt][2 * r + 1] - mn);
                    sacc[nt][2 * r] = p0;
                    sacc[nt][2 * r + 1] = p1;
                    rs += p0 + p1;
                }
                rs += __shfl_xor_sync(0xffffffffu, rs, 1);
                rs += __shfl_xor_sync(0xffffffffu, rs, 2);
                lrow[r] = lrow[r] * al + rs;
#pragma unroll
                for (int nt = 0; nt < 16; ++nt) {
                    oacc[nt][2 * r]     *= al;
                    oacc[nt][2 * r + 1] *= al;
                }
            }

            // O += P @ V  (4 k16 steps over kv, 16 d-tiles)
#pragma unroll
            for (int j = 0; j < 4; ++j) {
                uint32_t a[4];
                a[0] = packh2(sacc[2 * j][0],     sacc[2 * j][1]);
                a[1] = packh2(sacc[2 * j][2],     sacc[2 * j][3]);
                a[2] = packh2(sacc[2 * j + 1][0], sacc[2 * j + 1][1]);
                a[3] = packh2(sacc[2 * j + 1][2], sacc[2 * j + 1][3]);
#pragma unroll
                for (int dp = 0; dp < 8; ++dp) {
                    uint32_t bf[4];
                    ldsm_x4_t(bf, va + j * 16 * (FA_STR * 2) + dp * 32);
                    mma16816h(oacc[dp * 2],     a, bf);
                    mma16816h(oacc[dp * 2 + 1], a, bf + 2);
                }
            }
        }
    }

    // Epilogue: normalize and write fp32 O
#pragma unroll
    for (int r = 0; r < 2; ++r) {
        float inv = 1.0f / lrow[r];
        int row = q0 + wq0 + (lane >> 2) + r * 8;
        float* Og = O + (size_t)(b * Ss_ + row) * Dd_ + h * HD_;
#pragma unroll
        for (int nt = 0; nt < 16; ++nt) {
            int col = nt * 8 + (lane & 3) * 2;
            *(float2*)(Og + col) =
                make_float2(oacc[nt][2 * r] * inv, oacc[nt][2 * r + 1] * inv);
        }
    }
}

// ---------------------------------------------------------------------------
// Launch
// ---------------------------------------------------------------------------
extern "C" void kernel_launch(void* const* d_in, const int* in_sizes, int n_in,
                              void* d_out, int out_size)
{
    const float* x  = (const float*)d_in[0];
    const float* Wq = (const float*)d_in[2];
    const float* Wk = (const float*)d_in[3];
    const float* Wv = (const float*)d_in[4];
    const float* Wo = (const float*)d_in[5];
    float* out = (float*)d_out;

    float *Qp, *Kp, *Vp, *Op;
    __nv_bfloat16 *Ahp, *Alp, *Bhp, *Blp;
    __half *Qhp, *Khp, *Vhp;
    cudaGetSymbolAddress((void**)&Qp, g_Q);
    cudaGetSymbolAddress((void**)&Kp, g_K);
    cudaGetSymbolAddress((void**)&Vp, g_V);
    cudaGetSymbolAddress((void**)&Op, g_O);
    cudaGetSymbolAddress((void**)&Ahp, g_Ah);
    cudaGetSymbolAddress((void**)&Alp, g_Al);
    cudaGetSymbolAddress((void**)&Bhp, g_Bh);
    cudaGetSymbolAddress((void**)&Blp, g_Bl);
    cudaGetSymbolAddress((void**)&Qhp, g_Qh);
    cudaGetSymbolAddress((void**)&Khp, g_Kh);
    cudaGetSymbolAddress((void**)&Vhp, g_Vh);

    cudaFuncSetAttribute(gemm_tc, cudaFuncAttributeMaxDynamicSharedMemorySize,
                         GEMM_SMEM_BYTES);
    cudaFuncSetAttribute(flash_tc, cudaFuncAttributeMaxDynamicSharedMemorySize,
                         FA_SMEM);

    const int nX  = MROWS * Dd_;
    const int nWq = Dd_ * Dd_;
    const int nWk = Dd_ * NKV;
    const int nKV = MROWS * NKV;

    // x -> bf16 hi/lo (A side)
    convert_split_k<<<nX / 1024, 256>>>(x, Ahp, Alp, nX);

    // Q = x @ Wq
    convert_split_k<<<nWq / 1024, 256>>>(Wq, Bhp, Blp, nWq);
    gemm_tc<<<dim3(Dd_ / 128, MROWS / 128), 256, GEMM_SMEM_BYTES>>>(
        Ahp, Alp, Bhp, Blp, Qp, MROWS, Dd_, Dd_);

    // K = x @ Wk
    convert_split_k<<<nWk / 1024, 256>>>(Wk, Bhp, Blp, nWk);
    gemm_tc<<<dim3(NKV / 128, MROWS / 128), 256, GEMM_SMEM_BYTES>>>(
        Ahp, Alp, Bhp, Blp, Kp, MROWS, NKV, Dd_);

    // V = x @ Wv
    convert_split_k<<<nWk / 1024, 256>>>(Wv, Bhp, Blp, nWk);
    gemm_tc<<<dim3(NKV / 128, MROWS / 128), 256, GEMM_SMEM_BYTES>>>(
        Ahp, Alp, Bhp, Blp, Vp, MROWS, NKV, Dd_);

    // RoPE
    {
        int totq = MROWS * Hh_ * 64;
        rope_kernel<<<(totq + 255) / 256, 256>>>(Qp, Hh_, totq);
        int totk = MROWS * HKV_ * 64;
        rope_kernel<<<(totk + 255) / 256, 256>>>(Kp, HKV_, totk);
    }

    // fp32 -> fp16 for attention (scale*log2e folded into Q)
    const float qmult = 1.4426950408889634f / sqrtf((float)HD_);
    convert_half_k<<<nX / 2048, 256>>>(Qp, Qhp, nX, qmult);
    convert_half_k<<<nKV / 2048, 256>>>(Kp, Khp, nKV, 1.0f);
    convert_half_k<<<nKV / 2048, 256>>>(Vp, Vhp, nKV, 1.0f);

    // Flash attention (tensor cores)
    flash_tc<<<dim3(Ss_ / FA_BQ, Hh_, Bb_), 256, FA_SMEM>>>(Qhp, Khp, Vhp, Op);

    // out = O @ Wo
    convert_split_k<<<nX / 1024, 256>>>(Op, Ahp, Alp, nX);
    convert_split_k<<<nWq / 1024, 256>>>(Wo, Bhp, Blp, nWq);
    gemm_tc<<<dim3(Dd_ / 128, MROWS / 128), 256, GEMM_SMEM_BYTES>>>(
        Ahp, Alp, Bhp, Blp, out, MROWS, Dd_, Dd_);
}